// round 8
// baseline (speedup 1.0000x reference)
#include <cuda_runtime.h>
#include <cstdint>
#include <math.h>

#define NPTS    4096
#define MAXQ    32768             // B=8 * 4096
#define THREADS 256
#define QPT     4                 // queries per thread (2 packed f32x2 pairs)
#define QPB     (THREADS * QPT)   // 1024 queries per block
#define JCHUNK  256               // candidates per block
#define NCHUNK  (NPTS / JCHUNK)   // 16
#define NGROUP  32                // argmin recovery granularity
#define NGROUPS (JCHUNK / NGROUP) // 8
#define MLANES  8                 // merge lanes per query

typedef unsigned long long ull;

// Global best per (dir, query): (fkey(e_min) << 32) | group_start_within_batch
__device__ ull g_best[2][MAXQ];

__device__ __forceinline__ ull fma2(ull a, ull b, ull c) {
    ull d;
    asm("fma.rn.f32x2 %0, %1, %2, %3;" : "=l"(d) : "l"(a), "l"(b), "l"(c));
    return d;
}
__device__ __forceinline__ ull pack2(float lo, float hi) {
    ull d;
    asm("mov.b64 %0, {%1, %2};" : "=l"(d) : "f"(lo), "f"(hi));
    return d;
}
__device__ __forceinline__ ull dup2(float v) {
    ull d;
    asm("mov.b64 %0, {%1, %1};" : "=l"(d) : "f"(v));
    return d;
}
__device__ __forceinline__ float lof(ull v) { return __uint_as_float((unsigned int)v); }
__device__ __forceinline__ float hif(ull v) { return __uint_as_float((unsigned int)(v >> 32)); }

// Order-preserving float -> uint32 (total order incl. negatives).
__device__ __forceinline__ unsigned int fkey(float f) {
    unsigned int b = __float_as_uint(f);
    return (b & 0x80000000u) ? ~b : (b | 0x80000000u);
}

__global__ void __launch_bounds__(THREADS) init_kernel(float* out) {
    int i = blockIdx.x * THREADS + threadIdx.x;          // 0 .. MAXQ/2-1
    ulonglong2 v = make_ulonglong2(~0ull, ~0ull);
    ((ulonglong2*)g_best[0])[i] = v;
    ((ulonglong2*)g_best[1])[i] = v;
    if (i == 0) out[0] = 0.0f;
}

// NN kernel: per query, min over candidates of e = |c|^2 - 2<q,c>
// (argmin(e) == argmin(d)). Queries packed 2-per-f32x2 in registers;
// candidates duplicated in smem (broadcast LDS.128). Two candidates per
// iteration: 4 independent FFMA2 chains + 8 independent FMNMX accumulators
// so the scheduling window always holds issuable fma work.
// Cross-chunk reduction via fire-and-forget atomicMin(u64).
__global__ void __launch_bounds__(THREADS, 5) nn_kernel(
    const float* __restrict__ X1, const float* __restrict__ X2)
{
    __shared__ __align__(16) ull tile[JCHUNK][4];   // {xx, yy, zz, ww} dup'd

    const int dir   = blockIdx.z;              // 0: Q=X1,C=X2   1: Q=X2,C=X1
    const float* __restrict__ Q = dir ? X2 : X1;
    const float* __restrict__ C = dir ? X1 : X2;

    const int tid   = threadIdx.x;
    const int chunk = blockIdx.x;              // 0..NCHUNK-1
    const int qbase = blockIdx.y * QPB;
    const int batch = qbase / NPTS;            // QPB divides NPTS
    const int jloc  = chunk * JCHUNK;          // candidate base within batch

    {
        const float* p = C + (size_t)(batch * NPTS + jloc + tid) * 6;
        float x = p[0], y = p[1], z = p[2];
        tile[tid][0] = dup2(x);
        tile[tid][1] = dup2(y);
        tile[tid][2] = dup2(z);
        tile[tid][3] = dup2(fmaf(x, x, fmaf(y, y, z * z)));
    }
    __syncthreads();

    // 4 consecutive queries per thread; -2 folded in (exact scaling).
    const int q0 = qbase + tid * QPT;
    ull qx01, qy01, qz01, qx23, qy23, qz23;
    {
        const float* a = Q + (size_t)q0 * 6;
        qx01 = pack2(-2.0f * a[0],  -2.0f * a[6]);
        qy01 = pack2(-2.0f * a[1],  -2.0f * a[7]);
        qz01 = pack2(-2.0f * a[2],  -2.0f * a[8]);
        qx23 = pack2(-2.0f * a[12], -2.0f * a[18]);
        qy23 = pack2(-2.0f * a[13], -2.0f * a[19]);
        qz23 = pack2(-2.0f * a[14], -2.0f * a[20]);
    }

    float beste[QPT];
    int   bestg[QPT];
#pragma unroll
    for (int k = 0; k < QPT; k++) { beste[k] = 3.4e38f; bestg[k] = 0; }

    const ulonglong2* tp = (const ulonglong2*)&tile[0][0];
#pragma unroll 1
    for (int g = 0; g < NGROUPS; g++) {
        // 8 independent accumulators: a* for even candidate, b* for odd.
        float a0 = 3.4e38f, a1 = 3.4e38f, a2 = 3.4e38f, a3 = 3.4e38f;
        float b0 = 3.4e38f, b1 = 3.4e38f, b2 = 3.4e38f, b3 = 3.4e38f;
#pragma unroll 4
        for (int cc = 0; cc < NGROUP / 2; cc++) {      // 2 candidates / iter
            ulonglong2 A0 = tp[0];                     // cand even: xx, yy
            ulonglong2 B0 = tp[1];                     // cand even: zz, ww
            ulonglong2 A1 = tp[2];                     // cand odd
            ulonglong2 B1 = tp[3];
            tp += 4;
            ull t0 = fma2(qz01, B0.x, B0.y);
            ull t1 = fma2(qz23, B0.x, B0.y);
            ull u0 = fma2(qz01, B1.x, B1.y);
            ull u1 = fma2(qz23, B1.x, B1.y);
            t0 = fma2(qy01, A0.y, t0);
            t1 = fma2(qy23, A0.y, t1);
            u0 = fma2(qy01, A1.y, u0);
            u1 = fma2(qy23, A1.y, u1);
            t0 = fma2(qx01, A0.x, t0);                 // e(q0,q1 | even)
            t1 = fma2(qx23, A0.x, t1);                 // e(q2,q3 | even)
            u0 = fma2(qx01, A1.x, u0);                 // e(q0,q1 | odd)
            u1 = fma2(qx23, A1.x, u1);                 // e(q2,q3 | odd)
            a0 = fminf(a0, lof(t0));
            a1 = fminf(a1, hif(t0));
            a2 = fminf(a2, lof(t1));
            a3 = fminf(a3, hif(t1));
            b0 = fminf(b0, lof(u0));
            b1 = fminf(b1, hif(u0));
            b2 = fminf(b2, lof(u1));
            b3 = fminf(b3, hif(u1));
        }
        float g0 = fminf(a0, b0), g1 = fminf(a1, b1);
        float g2 = fminf(a2, b2), g3 = fminf(a3, b3);
        if (g0 < beste[0]) { beste[0] = g0; bestg[0] = g; }
        if (g1 < beste[1]) { beste[1] = g1; bestg[1] = g; }
        if (g2 < beste[2]) { beste[2] = g2; bestg[2] = g; }
        if (g3 < beste[3]) { beste[3] = g3; bestg[3] = g; }
    }

#pragma unroll
    for (int k = 0; k < QPT; k++) {
        unsigned int start = (unsigned int)(jloc + bestg[k] * NGROUP);
        atomicMin(&g_best[dir][q0 + k], ((ull)fkey(beste[k]) << 32) | start);
    }
}

__device__ __forceinline__ float normal_diff2(const float* __restrict__ a,
                                              const float* __restrict__ b) {
    float ax = a[0], ay = a[1], az = a[2];
    float bx = b[0], by = b[1], bz = b[2];
    float ia = 1.0f / fmaxf(sqrtf(fmaf(ax, ax, fmaf(ay, ay, az * az))), 1e-12f);
    float ib = 1.0f / fmaxf(sqrtf(fmaf(bx, bx, fmaf(by, by, bz * bz))), 1e-12f);
    float dx = ax * ia - bx * ib;
    float dy = ay * ia - by * ib;
    float dz = az * ia - bz * ib;
    return fmaf(dx, dx, fmaf(dy, dy, dz * dz));
}

// Merge: 8 lanes per query. Read the winning (e, group-start) record, rescan
// the 32-candidate group with the bit-identical scalar chain (4 per lane,
// high MLP), cross-lane argmin via packed (fkey << 32 | local_idx), lane 0
// computes the contribution; block partial -> one atomicAdd.
__global__ void __launch_bounds__(THREADS) merge_kernel(
    const float* __restrict__ X1, const float* __restrict__ X2,
    float* __restrict__ out, int nq, float inv_nq)
{
    const int tid  = threadIdx.x;
    const int l    = tid & (MLANES - 1);
    const int gi   = (blockIdx.x * THREADS + tid) / MLANES;   // query slot
    const int dir  = gi >= nq;
    const int q    = dir ? gi - nq : gi;
    const int batch = q / NPTS;

    ull best = g_best[dir][q];                 // broadcast load
    int start = (int)(best & 0xFFFFFFFFull);   // within batch

    const float* __restrict__ Qb = dir ? X2 : X1;
    const float* __restrict__ Cb = dir ? X1 : X2;
    const float* qp = Qb + (size_t)q * 6;
    float qx = qp[0], qy = qp[1], qz = qp[2];
    float nxs = -2.0f * qx, nys = -2.0f * qy, nzs = -2.0f * qz;

    const float2* cb2 = (const float2*)(Cb + (size_t)(batch * NPTS + start + l * 4) * 6);
    float2 f0[4], f1[4];
#pragma unroll
    for (int j = 0; j < 4; j++) {              // 8 independent LDG.64
        f0[j] = cb2[j * 3 + 0];                // x, y
        f1[j] = cb2[j * 3 + 1];                // z, nx
    }
    float be = 3.4e38f;
    int   bi = 0;
#pragma unroll
    for (int j = 0; j < 4; j++) {
        float cx = f0[j].x, cy = f0[j].y, cz = f1[j].x;
        float cw = fmaf(cx, cx, fmaf(cy, cy, cz * cz));
        float t  = fmaf(nxs, cx, fmaf(nys, cy, fmaf(nzs, cz, cw)));
        if (t < be) { be = t; bi = j; }        // strict <: first min
    }
    ull bk = ((ull)fkey(be) << 32) | (unsigned int)(l * 4 + bi);
#pragma unroll
    for (int m = MLANES / 2; m >= 1; m >>= 1) {
        ull o = __shfl_xor_sync(0xFFFFFFFFu, bk, m);
        bk = o < bk ? o : bk;                  // tie -> smaller idx
    }

    float acc = 0.0f;
    if (l == 0) {
        int idx = start + (int)(bk & 31u);
        unsigned int ek = (unsigned int)(bk >> 32);
        float e = __uint_as_float((ek & 0x80000000u) ? (ek & 0x7FFFFFFFu) : ~ek);
        float sq = fmaf(qx, qx, fmaf(qy, qy, qz * qz));
        const float* cn = Cb + (size_t)(batch * NPTS + idx) * 6 + 3;
        acc = (sq + e) + normal_diff2(qp + 3, cn);
    }

    __shared__ float ssum[THREADS / 32];
    float v = acc;
#pragma unroll
    for (int o = 16; o > 0; o >>= 1) v += __shfl_down_sync(0xFFFFFFFFu, v, o);
    int lane = tid & 31, warp = tid >> 5;
    if (lane == 0) ssum[warp] = v;
    __syncthreads();
    if (warp == 0) {
        v = (lane < THREADS / 32) ? ssum[lane] : 0.0f;
#pragma unroll
        for (int o = 4; o > 0; o >>= 1) v += __shfl_down_sync(0xFFFFFFFFu, v, o);
        if (lane == 0) atomicAdd(out, v * inv_nq);
    }
}

extern "C" void kernel_launch(void* const* d_in, const int* in_sizes, int n_in,
                              void* d_out, int out_size)
{
    const float* x1 = (const float*)d_in[0];
    const float* x2 = (const float*)d_in[1];
    float* out = (float*)d_out;

    int total = in_sizes[0];
    int B  = total / (NPTS * 6);      // 8
    int nq = B * NPTS;                // 32768

    init_kernel<<<MAXQ / 2 / THREADS, THREADS>>>(out);   // 64 blocks, u64x2 stores

    dim3 grid(NCHUNK, nq / QPB, 2);   // (16, 32, 2) = 1024 CTAs
    nn_kernel<<<grid, THREADS>>>(x1, x2);

    int mblocks = 2 * nq * MLANES / THREADS;   // 2048
    merge_kernel<<<mblocks, THREADS>>>(x1, x2, out, nq, 1.0f / (float)nq);
}

// round 9
// speedup vs baseline: 1.1230x; 1.1230x over previous
#include <cuda_runtime.h>
#include <cstdint>
#include <math.h>

#define NPTS    4096
#define MAXQ    32768             // B=8 * 4096
#define THREADS 256
#define QPT     4                 // queries per thread (dup'd into f32x2)
#define QPB     (THREADS * QPT)   // 1024 queries per block
#define JCHUNK  128               // candidates per block
#define NCHUNK  (NPTS / JCHUNK)   // 32
#define NGROUP  32                // argmin recovery granularity
#define NGROUPS (JCHUNK / NGROUP) // 4
#define MLANES  8                 // merge lanes per query

typedef unsigned long long ull;

// Zero-initialized. Holds ~((fkey(e_min)<<32)|group_start): larger = better,
// so nn uses atomicMax and 0 is the empty sentinel. merge resets to 0 after
// reading, so every graph replay starts from the same state.
__device__ ull g_best[2][MAXQ];

__device__ __forceinline__ ull fma2(ull a, ull b, ull c) {
    ull d;
    asm("fma.rn.f32x2 %0, %1, %2, %3;" : "=l"(d) : "l"(a), "l"(b), "l"(c));
    return d;
}
__device__ __forceinline__ ull dup2(float v) {
    ull d;
    asm("mov.b64 %0, {%1, %1};" : "=l"(d) : "f"(v));
    return d;
}
__device__ __forceinline__ float lof(ull v) { return __uint_as_float((unsigned int)v); }
__device__ __forceinline__ float hif(ull v) { return __uint_as_float((unsigned int)(v >> 32)); }

// Order-preserving float -> uint32 (total order incl. negatives).
__device__ __forceinline__ unsigned int fkey(float f) {
    unsigned int b = __float_as_uint(f);
    return (b & 0x80000000u) ? ~b : (b | 0x80000000u);
}

// NN kernel: per query, min over candidates of e = |c|^2 - 2<q,c>
// (argmin(e) == argmin(d)). Candidates packed 2-per-f32x2 via an interleaved
// SoA tile (1 LDS.128 = {x0,x1,y0,y1} of a candidate pair); queries dup'd in
// registers. Body per 2 cands: 2 LDS + 12 FFMA2 + 8 FMNMX = 22 issues vs
// 24 fma-pipe cycles -> issue slack. Cross-chunk reduce via atomicMax of
// inverted keys into the zero-initialized g_best.
__global__ void __launch_bounds__(THREADS, 4) nn_kernel(
    const float* __restrict__ X1, const float* __restrict__ X2, float* out)
{
    // pair p: sA = {x_2p, x_2p+1, y_2p, y_2p+1}, sB = {z.., w..}
    __shared__ __align__(16) float sA[JCHUNK * 2];
    __shared__ __align__(16) float sB[JCHUNK * 2];

    const int dir   = blockIdx.z;              // 0: Q=X1,C=X2   1: Q=X2,C=X1
    const float* __restrict__ Q = dir ? X2 : X1;
    const float* __restrict__ C = dir ? X1 : X2;

    const int tid   = threadIdx.x;
    const int chunk = blockIdx.x;              // 0..NCHUNK-1
    const int qbase = blockIdx.y * QPB;
    const int batch = qbase / NPTS;            // QPB divides NPTS
    const int jloc  = chunk * JCHUNK;          // candidate base within batch

    if (dir == 0 && chunk == 0 && blockIdx.y == 0 && tid == 0)
        out[0] = 0.0f;                         // merge accumulates into out

    if (tid < JCHUNK) {
        const float* p = C + (size_t)(batch * NPTS + jloc + tid) * 6;
        float x = p[0], y = p[1], z = p[2];
        int pr = tid >> 1, o = tid & 1;
        sA[pr * 4 + o]     = x;
        sA[pr * 4 + 2 + o] = y;
        sB[pr * 4 + o]     = z;
        sB[pr * 4 + 2 + o] = fmaf(x, x, fmaf(y, y, z * z));
    }
    __syncthreads();

    // 4 consecutive queries per thread, dup'd; -2 folded in (exact).
    const int q0 = qbase + tid * QPT;
    ull qx[QPT], qy[QPT], qz[QPT];
#pragma unroll
    for (int k = 0; k < QPT; k++) {
        const float* a = Q + (size_t)(q0 + k) * 6;
        qx[k] = dup2(-2.0f * a[0]);
        qy[k] = dup2(-2.0f * a[1]);
        qz[k] = dup2(-2.0f * a[2]);
    }

    float beste[QPT];
    int   bestg[QPT];
#pragma unroll
    for (int k = 0; k < QPT; k++) { beste[k] = 3.4e38f; bestg[k] = 0; }

    const ulonglong2* pA = (const ulonglong2*)sA;
    const ulonglong2* pB = (const ulonglong2*)sB;

#pragma unroll 1
    for (int g = 0; g < NGROUPS; g++) {
        float g0[QPT], g1[QPT];    // even / odd candidate accumulators
#pragma unroll
        for (int k = 0; k < QPT; k++) { g0[k] = 3.4e38f; g1[k] = 3.4e38f; }

#pragma unroll 4
        for (int pp = 0; pp < NGROUP / 2; pp++) {      // candidate pairs
            int p = g * (NGROUP / 2) + pp;
            ulonglong2 AB = pA[p];                     // x01, y01
            ulonglong2 CD = pB[p];                     // z01, w01
#pragma unroll
            for (int k = 0; k < QPT; k++) {
                ull t = fma2(qz[k], CD.x, CD.y);       // z*cz + |c|^2
                t = fma2(qy[k], AB.y, t);
                t = fma2(qx[k], AB.x, t);              // e for cand pair
                g0[k] = fminf(g0[k], lof(t));
                g1[k] = fminf(g1[k], hif(t));
            }
        }
#pragma unroll
        for (int k = 0; k < QPT; k++) {
            float gm = fminf(g0[k], g1[k]);
            if (gm < beste[k]) { beste[k] = gm; bestg[k] = g; }
        }
    }

#pragma unroll
    for (int k = 0; k < QPT; k++) {
        unsigned int start = (unsigned int)(jloc + bestg[k] * NGROUP);
        ull key = ((ull)fkey(beste[k]) << 32) | start;
        atomicMax(&g_best[dir][q0 + k], ~key);         // inverted: max == best
    }
}

__device__ __forceinline__ float normal_diff2(const float* __restrict__ a,
                                              const float* __restrict__ b) {
    float ax = a[0], ay = a[1], az = a[2];
    float bx = b[0], by = b[1], bz = b[2];
    float ia = 1.0f / fmaxf(sqrtf(fmaf(ax, ax, fmaf(ay, ay, az * az))), 1e-12f);
    float ib = 1.0f / fmaxf(sqrtf(fmaf(bx, bx, fmaf(by, by, bz * bz))), 1e-12f);
    float dx = ax * ia - bx * ib;
    float dy = ay * ia - by * ib;
    float dz = az * ia - bz * ib;
    return fmaf(dx, dx, fmaf(dy, dy, dz * dz));
}

// Merge: 8 lanes per query. Read winning (e, group-start), reset the slot to
// zero (for the next graph replay), rescan the 32-candidate group with the
// bit-identical scalar chain (4 per lane, high MLP), cross-lane argmin via
// packed (fkey << 32 | local_idx); lane 0 adds contribution; block partial ->
// one atomicAdd.
__global__ void __launch_bounds__(THREADS) merge_kernel(
    const float* __restrict__ X1, const float* __restrict__ X2,
    float* __restrict__ out, int nq, float inv_nq)
{
    const int tid  = threadIdx.x;
    const int l    = tid & (MLANES - 1);
    const int gi   = (blockIdx.x * THREADS + tid) / MLANES;   // query slot
    const int dir  = gi >= nq;
    const int q    = dir ? gi - nq : gi;
    const int batch = q / NPTS;

    ull best = ~g_best[dir][q];                // un-invert (broadcast load)
    if (l == 0) g_best[dir][q] = 0ull;         // reset for next replay
    int start = (int)(best & 0xFFFFFFFFull);   // within batch

    const float* __restrict__ Qb = dir ? X2 : X1;
    const float* __restrict__ Cb = dir ? X1 : X2;
    const float* qp = Qb + (size_t)q * 6;
    float qx = qp[0], qy = qp[1], qz = qp[2];
    float nxs = -2.0f * qx, nys = -2.0f * qy, nzs = -2.0f * qz;

    const float2* cb2 = (const float2*)(Cb + (size_t)(batch * NPTS + start + l * 4) * 6);
    float2 f0[4], f1[4];
#pragma unroll
    for (int j = 0; j < 4; j++) {              // 8 independent LDG.64
        f0[j] = cb2[j * 3 + 0];                // x, y
        f1[j] = cb2[j * 3 + 1];                // z, nx
    }
    float be = 3.4e38f;
    int   bi = 0;
#pragma unroll
    for (int j = 0; j < 4; j++) {
        float cx = f0[j].x, cy = f0[j].y, cz = f1[j].x;
        float cw = fmaf(cx, cx, fmaf(cy, cy, cz * cz));
        float t  = fmaf(nxs, cx, fmaf(nys, cy, fmaf(nzs, cz, cw)));
        if (t < be) { be = t; bi = j; }        // strict <: first min
    }
    ull bk = ((ull)fkey(be) << 32) | (unsigned int)(l * 4 + bi);
#pragma unroll
    for (int m = MLANES / 2; m >= 1; m >>= 1) {
        ull o = __shfl_xor_sync(0xFFFFFFFFu, bk, m);
        bk = o < bk ? o : bk;                  // tie -> smaller idx
    }

    float acc = 0.0f;
    if (l == 0) {
        int idx = start + (int)(bk & 31u);
        unsigned int ek = (unsigned int)(bk >> 32);
        float e = __uint_as_float((ek & 0x80000000u) ? (ek & 0x7FFFFFFFu) : ~ek);
        float sq = fmaf(qx, qx, fmaf(qy, qy, qz * qz));
        const float* cn = Cb + (size_t)(batch * NPTS + idx) * 6 + 3;
        acc = (sq + e) + normal_diff2(qp + 3, cn);
    }

    __shared__ float ssum[THREADS / 32];
    float v = acc;
#pragma unroll
    for (int o = 16; o > 0; o >>= 1) v += __shfl_down_sync(0xFFFFFFFFu, v, o);
    int lane = tid & 31, warp = tid >> 5;
    if (lane == 0) ssum[warp] = v;
    __syncthreads();
    if (warp == 0) {
        v = (lane < THREADS / 32) ? ssum[lane] : 0.0f;
#pragma unroll
        for (int o = 4; o > 0; o >>= 1) v += __shfl_down_sync(0xFFFFFFFFu, v, o);
        if (lane == 0) atomicAdd(out, v * inv_nq);
    }
}

extern "C" void kernel_launch(void* const* d_in, const int* in_sizes, int n_in,
                              void* d_out, int out_size)
{
    const float* x1 = (const float*)d_in[0];
    const float* x2 = (const float*)d_in[1];
    float* out = (float*)d_out;

    int total = in_sizes[0];
    int B  = total / (NPTS * 6);      // 8
    int nq = B * NPTS;                // 32768

    dim3 grid(NCHUNK, nq / QPB, 2);   // (32, 32, 2) = 2048 CTAs
    nn_kernel<<<grid, THREADS>>>(x1, x2, out);

    int mblocks = 2 * nq * MLANES / THREADS;   // 2048
    merge_kernel<<<mblocks, THREADS>>>(x1, x2, out, nq, 1.0f / (float)nq);
}

// round 11
// speedup vs baseline: 1.1967x; 1.0656x over previous
#include <cuda_runtime.h>
#include <cstdint>
#include <math.h>

#define NPTS    4096
#define MAXQ    32768             // B=8 * 4096
#define THREADS 256
#define QPT     4                 // queries per thread (dup'd into f32x2)
#define QPB     (THREADS * QPT)   // 1024 queries per block
#define JCHUNK  128               // candidates per block
#define NCHUNK  (NPTS / JCHUNK)   // 32
#define NGROUP  16                // argmin recovery granularity
#define NGROUPS (JCHUNK / NGROUP) // 8
#define MLANES  4                 // merge lanes per query

typedef unsigned long long ull;

// Zero-initialized. Holds ~((fkey(e_min)<<32)|group_start): larger = better,
// so nn uses atomicMax and 0 is the empty sentinel. merge resets to 0 after
// reading, so every graph replay starts from identical state.
__device__ ull g_best[2][MAXQ];

__device__ __forceinline__ ull fma2(ull a, ull b, ull c) {
    ull d;
    asm("fma.rn.f32x2 %0, %1, %2, %3;" : "=l"(d) : "l"(a), "l"(b), "l"(c));
    return d;
}
__device__ __forceinline__ ull dup2(float v) {
    ull d;
    asm("mov.b64 %0, {%1, %1};" : "=l"(d) : "f"(v));
    return d;
}
__device__ __forceinline__ float lof(ull v) { return __uint_as_float((unsigned int)v); }
__device__ __forceinline__ float hif(ull v) { return __uint_as_float((unsigned int)(v >> 32)); }

// Order-preserving float -> uint32 (total order incl. negatives).
__device__ __forceinline__ unsigned int fkey(float f) {
    unsigned int b = __float_as_uint(f);
    return (b & 0x80000000u) ? ~b : (b | 0x80000000u);
}

// NN kernel: per query, min over candidates of e = |c|^2 - 2<q,c>
// (argmin(e) == argmin(d)). Candidates packed 2-per-f32x2 via interleaved
// SoA tile (1 LDS.128 = {x0,x1,y0,y1} of a candidate pair); queries dup'd
// in registers. Body per 2 cands: 2 LDS + 12 FFMA2 + 8 FMNMX = 22 issues
// vs 24 fma-pipe cycles -> issue slack. Cross-chunk reduce via atomicMax
// of inverted keys into the zero-initialized g_best.
__global__ void __launch_bounds__(THREADS, 4) nn_kernel(
    const float* __restrict__ X1, const float* __restrict__ X2, float* out)
{
    // pair p: sA = {x_2p, x_2p+1, y_2p, y_2p+1}, sB = {z.., w..}
    __shared__ __align__(16) float sA[JCHUNK * 2];
    __shared__ __align__(16) float sB[JCHUNK * 2];

    const int dir   = blockIdx.z;              // 0: Q=X1,C=X2   1: Q=X2,C=X1
    const float* __restrict__ Q = dir ? X2 : X1;
    const float* __restrict__ C = dir ? X1 : X2;

    const int tid   = threadIdx.x;
    const int chunk = blockIdx.x;              // 0..NCHUNK-1
    const int qbase = blockIdx.y * QPB;
    const int batch = qbase / NPTS;            // QPB divides NPTS
    const int jloc  = chunk * JCHUNK;          // candidate base within batch

    if (dir == 0 && chunk == 0 && blockIdx.y == 0 && tid == 0)
        out[0] = 0.0f;                         // merge accumulates into out

    if (tid < JCHUNK) {
        const float* p = C + (size_t)(batch * NPTS + jloc + tid) * 6;
        float x = p[0], y = p[1], z = p[2];
        int pr = tid >> 1, o = tid & 1;
        sA[pr * 4 + o]     = x;
        sA[pr * 4 + 2 + o] = y;
        sB[pr * 4 + o]     = z;
        sB[pr * 4 + 2 + o] = fmaf(x, x, fmaf(y, y, z * z));
    }
    __syncthreads();

    // 4 consecutive queries per thread, dup'd; -2 folded in (exact).
    const int q0 = qbase + tid * QPT;
    ull qx[QPT], qy[QPT], qz[QPT];
#pragma unroll
    for (int k = 0; k < QPT; k++) {
        const float* a = Q + (size_t)(q0 + k) * 6;
        qx[k] = dup2(-2.0f * a[0]);
        qy[k] = dup2(-2.0f * a[1]);
        qz[k] = dup2(-2.0f * a[2]);
    }

    float beste[QPT];
    int   bestg[QPT];
#pragma unroll
    for (int k = 0; k < QPT; k++) { beste[k] = 3.4e38f; bestg[k] = 0; }

    const ulonglong2* pA = (const ulonglong2*)sA;
    const ulonglong2* pB = (const ulonglong2*)sB;

#pragma unroll 1
    for (int g = 0; g < NGROUPS; g++) {
        float g0[QPT], g1[QPT];    // even / odd candidate accumulators
#pragma unroll
        for (int k = 0; k < QPT; k++) { g0[k] = 3.4e38f; g1[k] = 3.4e38f; }

#pragma unroll 4
        for (int pp = 0; pp < NGROUP / 2; pp++) {      // candidate pairs
            int p = g * (NGROUP / 2) + pp;
            ulonglong2 AB = pA[p];                     // x01, y01
            ulonglong2 CD = pB[p];                     // z01, w01
#pragma unroll
            for (int k = 0; k < QPT; k++) {
                ull t = fma2(qz[k], CD.x, CD.y);       // z*cz + |c|^2
                t = fma2(qy[k], AB.y, t);
                t = fma2(qx[k], AB.x, t);              // e for cand pair
                g0[k] = fminf(g0[k], lof(t));
                g1[k] = fminf(g1[k], hif(t));
            }
        }
#pragma unroll
        for (int k = 0; k < QPT; k++) {
            float gm = fminf(g0[k], g1[k]);
            if (gm < beste[k]) { beste[k] = gm; bestg[k] = g; }
        }
    }

#pragma unroll
    for (int k = 0; k < QPT; k++) {
        unsigned int start = (unsigned int)(jloc + bestg[k] * NGROUP);
        ull key = ((ull)fkey(beste[k]) << 32) | start;
        atomicMax(&g_best[dir][q0 + k], ~key);         // inverted: max == best
    }
}

__device__ __forceinline__ float normal_diff2(const float* __restrict__ a,
                                              const float* __restrict__ b) {
    float ax = a[0], ay = a[1], az = a[2];
    float bx = b[0], by = b[1], bz = b[2];
    float ia = 1.0f / fmaxf(sqrtf(fmaf(ax, ax, fmaf(ay, ay, az * az))), 1e-12f);
    float ib = 1.0f / fmaxf(sqrtf(fmaf(bx, bx, fmaf(by, by, bz * bz))), 1e-12f);
    float dx = ax * ia - bx * ib;
    float dy = ay * ia - by * ib;
    float dz = az * ia - bz * ib;
    return fmaf(dx, dx, fmaf(dy, dy, dz * dz));
}

// Merge: 4 lanes per query. Read winning (e, group-start), reset the slot
// (graph-replay determinism), rescan the 16-candidate group with the
// bit-identical scalar chain (4 per lane, high MLP), cross-lane argmin via
// packed (fkey << 32 | local_idx); lane 0 adds the contribution; block
// partial -> one atomicAdd.
__global__ void __launch_bounds__(THREADS) merge_kernel(
    const float* __restrict__ X1, const float* __restrict__ X2,
    float* __restrict__ out, int nq, float inv_nq)
{
    const int tid  = threadIdx.x;
    const int l    = tid & (MLANES - 1);
    const int gi   = (blockIdx.x * THREADS + tid) / MLANES;   // query slot
    const int dir  = gi >= nq;
    const int q    = dir ? gi - nq : gi;
    const int batch = q / NPTS;

    ull best = ~g_best[dir][q];                // un-invert (broadcast load)
    if (l == 0) g_best[dir][q] = 0ull;         // reset for next replay
    int start = (int)(best & 0xFFFFFFFFull);   // within batch

    const float* __restrict__ Qb = dir ? X2 : X1;
    const float* __restrict__ Cb = dir ? X1 : X2;
    const float* qp = Qb + (size_t)q * 6;
    float qx = qp[0], qy = qp[1], qz = qp[2];
    float nxs = -2.0f * qx, nys = -2.0f * qy, nzs = -2.0f * qz;

    const float2* cb2 = (const float2*)(Cb + (size_t)(batch * NPTS + start + l * 4) * 6);
    float2 f0[4], f1[4];
#pragma unroll
    for (int j = 0; j < 4; j++) {              // 8 independent LDG.64
        f0[j] = cb2[j * 3 + 0];                // x, y
        f1[j] = cb2[j * 3 + 1];                // z, nx
    }
    float be = 3.4e38f;
    int   bi = 0;
#pragma unroll
    for (int j = 0; j < 4; j++) {
        float cx = f0[j].x, cy = f0[j].y, cz = f1[j].x;
        float cw = fmaf(cx, cx, fmaf(cy, cy, cz * cz));
        float t  = fmaf(nxs, cx, fmaf(nys, cy, fmaf(nzs, cz, cw)));
        if (t < be) { be = t; bi = j; }        // strict <: first min
    }
    ull bk = ((ull)fkey(be) << 32) | (unsigned int)(l * 4 + bi);
#pragma unroll
    for (int m = MLANES / 2; m >= 1; m >>= 1) {
        ull o = __shfl_xor_sync(0xFFFFFFFFu, bk, m);
        bk = o < bk ? o : bk;                  // tie -> smaller idx
    }

    float acc = 0.0f;
    if (l == 0) {
        int idx = start + (int)(bk & (NGROUP - 1));
        unsigned int ek = (unsigned int)(bk >> 32);
        float e = __uint_as_float((ek & 0x80000000u) ? (ek & 0x7FFFFFFFu) : ~ek);
        float sq = fmaf(qx, qx, fmaf(qy, qy, qz * qz));
        const float* cn = Cb + (size_t)(batch * NPTS + idx) * 6 + 3;
        acc = (sq + e) + normal_diff2(qp + 3, cn);
    }

    __shared__ float ssum[THREADS / 32];
    float v = acc;
#pragma unroll
    for (int o = 16; o > 0; o >>= 1) v += __shfl_down_sync(0xFFFFFFFFu, v, o);
    int lane = tid & 31, warp = tid >> 5;
    if (lane == 0) ssum[warp] = v;
    __syncthreads();
    if (warp == 0) {
        v = (lane < THREADS / 32) ? ssum[lane] : 0.0f;
#pragma unroll
        for (int o = 4; o > 0; o >>= 1) v += __shfl_down_sync(0xFFFFFFFFu, v, o);
        if (lane == 0) atomicAdd(out, v * inv_nq);
    }
}

extern "C" void kernel_launch(void* const* d_in, const int* in_sizes, int n_in,
                              void* d_out, int out_size)
{
    const float* x1 = (const float*)d_in[0];
    const float* x2 = (const float*)d_in[1];
    float* out = (float*)d_out;

    int total = in_sizes[0];
    int B  = total / (NPTS * 6);      // 8
    int nq = B * NPTS;                // 32768

    dim3 grid(NCHUNK, nq / QPB, 2);   // (32, 32, 2) = 2048 CTAs
    nn_kernel<<<grid, THREADS>>>(x1, x2, out);

    int mblocks = 2 * nq * MLANES / THREADS;   // 1024
    merge_kernel<<<mblocks, THREADS>>>(x1, x2, out, nq, 1.0f / (float)nq);
}